// round 3
// baseline (speedup 1.0000x reference)
#include <cuda_runtime.h>
#include <cuda_bf16.h>
#include <math.h>

// Problem constants
#define B_SZ 8
#define L_SEQ 2048
#define H_DIM 1024
#define N_DIM 512
#define M_ROWS (B_SZ * L_SEQ)       // 16384
#define K_DIM  1024                  // both GEMMs have K=1024 (H, or 2N)
#define N_OUT  1024                  // both GEMMs have N=1024 (2N, or H)

// GEMM tiling
#define BM 128
#define BN 128
#define BK 16
#define TM 8
#define TN 8
#define NTHREADS 256

// Scratch: Bu / (xr|xi) buffer, 16384 x 1024 fp32 = 64 MB (static, allocation-free)
__device__ float g_scratch[(size_t)M_ROWS * N_OUT];

// ---------------------------------------------------------------------------
// GEMM1: g_scratch = u (16384x1024) @ [Br | Bi]  (1024x1024, halves ld=512)
// Each CTA's 128-col tile lies entirely in the real half or the imag half.
// ---------------------------------------------------------------------------
__global__ __launch_bounds__(NTHREADS)
void gemm1_kernel(const float* __restrict__ A,
                  const float* __restrict__ Br,
                  const float* __restrict__ Bi)
{
    __shared__ float As[BK][BM];
    __shared__ float Bs[BK][BN];

    const int bn0 = blockIdx.x * BN;          // output col block
    const int bm0 = blockIdx.y * BM;          // output row block
    const int tid = threadIdx.x;

    const float* Bsel = (bn0 < N_DIM) ? Br : Bi;
    const int bcol = bn0 & (N_DIM - 1);       // column within selected half

    const int trow = tid / 16;                // 0..15
    const int tcol = tid % 16;                // 0..15

    // Global-load mapping
    const int aRow  = tid / 4;                // 0..63 (+64 second pass)
    const int aCol4 = (tid % 4) * 4;          // 0,4,8,12
    const int bRow  = tid / 32;               // 0..7  (+8 second pass)
    const int bCol4 = (tid % 32) * 4;         // 0..124

    const float* Aptr = A + (size_t)bm0 * K_DIM;

    float acc[TM][TN];
#pragma unroll
    for (int i = 0; i < TM; i++)
#pragma unroll
        for (int j = 0; j < TN; j++) acc[i][j] = 0.f;

    for (int k0 = 0; k0 < K_DIM; k0 += BK) {
#pragma unroll
        for (int i = 0; i < 2; i++) {
            int r = aRow + i * 64;
            float4 v = *(const float4*)(Aptr + (size_t)r * K_DIM + k0 + aCol4);
            As[aCol4 + 0][r] = v.x;
            As[aCol4 + 1][r] = v.y;
            As[aCol4 + 2][r] = v.z;
            As[aCol4 + 3][r] = v.w;
        }
#pragma unroll
        for (int i = 0; i < 2; i++) {
            int r = bRow + i * 8;             // k within tile
            float4 v = *(const float4*)(Bsel + (size_t)(k0 + r) * N_DIM + bcol + bCol4);
            *(float4*)&Bs[r][bCol4] = v;
        }
        __syncthreads();

#pragma unroll
        for (int k = 0; k < BK; k++) {
            float ra[TM], rb[TN];
#pragma unroll
            for (int i = 0; i < TM; i++) ra[i] = As[k][trow * TM + i];
#pragma unroll
            for (int j = 0; j < TN; j++) rb[j] = Bs[k][tcol * TN + j];
#pragma unroll
            for (int i = 0; i < TM; i++)
#pragma unroll
                for (int j = 0; j < TN; j++)
                    acc[i][j] = fmaf(ra[i], rb[j], acc[i][j]);
        }
        __syncthreads();
    }

    float* Cp = g_scratch + (size_t)(bm0 + trow * TM) * N_OUT + bn0 + tcol * TN;
#pragma unroll
    for (int i = 0; i < TM; i++) {
#pragma unroll
        for (int j = 0; j < TN; j += 4) {
            float4 v = make_float4(acc[i][j], acc[i][j+1], acc[i][j+2], acc[i][j+3]);
            *(float4*)(Cp + (size_t)i * N_OUT + j) = v;
        }
    }
}

// ---------------------------------------------------------------------------
// Elementwise: Lambda^e * Bu, then cumsum over batch (axis 0), IN PLACE.
// Layout of g_scratch row r=b*L+l: cols [0,512) = real, [512,1024) = imag.
// One thread per (l, n); loops b = 0..7.
// ---------------------------------------------------------------------------
__global__ __launch_bounds__(256)
void lru_elem_kernel(const int* __restrict__ lengths,
                     const float* __restrict__ nu_log,
                     const float* __restrict__ theta_log)
{
    const int idx = blockIdx.x * blockDim.x + threadIdx.x;
    if (idx >= L_SEQ * N_DIM) return;
    const int l = idx / N_DIM;
    const int n = idx % N_DIM;

    // lam_mod = exp(-exp(nu_log)); mimic pow(lam_mod, e) = exp(e*log(lam_mod))
    const float lam_mod = expf(-expf(__ldg(&nu_log[n])));
    const float lam_log = logf(lam_mod);
    const float arg     = expf(__ldg(&theta_log[n]));

    // Batch all loads first (MLP)
    float br[B_SZ], bi[B_SZ];
    size_t base[B_SZ];
#pragma unroll
    for (int b = 0; b < B_SZ; b++) {
        base[b] = ((size_t)b * L_SEQ + l) * N_OUT + n;
        br[b] = g_scratch[base[b]];
        bi[b] = g_scratch[base[b] + N_DIM];
    }

    float xr = 0.f, xi = 0.f;
#pragma unroll
    for (int b = 0; b < B_SZ; b++) {
        float e = (float)__ldg(&lengths[b]) - (float)(l + 1);
        e = fmaxf(e, 0.f);
        float mag = expf(e * lam_log);
        float ang = e * arg;
        float s, c;
        sincosf(ang, &s, &c);
        float Lr = mag * c;
        float Li = mag * s;
        float pr = Lr * br[b] - Li * bi[b];
        float pi = Lr * bi[b] + Li * br[b];
        xr += pr;
        xi += pi;
        g_scratch[base[b]]         = xr;
        g_scratch[base[b] + N_DIM] = xi;
    }
}

// ---------------------------------------------------------------------------
// GEMM2: y = [xr|xi] (16384x1024) @ [Cr ; -Ci]  (1024x1024, ld=1024)
// K-tiles (BK=16) never straddle the Cr/Ci boundary (512 % 16 == 0):
// k < 512 -> Cr[k][h], k >= 512 -> -Ci[k-512][h].
// ---------------------------------------------------------------------------
__global__ __launch_bounds__(NTHREADS)
void gemm2_kernel(const float* __restrict__ Cr,
                  const float* __restrict__ Ci,
                  float* __restrict__ Y)
{
    __shared__ float As[BK][BM];
    __shared__ float Bs[BK][BN];

    const int bn0 = blockIdx.x * BN;
    const int bm0 = blockIdx.y * BM;
    const int tid = threadIdx.x;

    const int trow = tid / 16;
    const int tcol = tid % 16;

    const int aRow  = tid / 4;
    const int aCol4 = (tid % 4) * 4;
    const int bRow  = tid / 32;
    const int bCol4 = (tid % 32) * 4;

    const float* Aptr = g_scratch + (size_t)bm0 * K_DIM;

    float acc[TM][TN];
#pragma unroll
    for (int i = 0; i < TM; i++)
#pragma unroll
        for (int j = 0; j < TN; j++) acc[i][j] = 0.f;

    for (int k0 = 0; k0 < K_DIM; k0 += BK) {
        const bool imagHalf = (k0 >= N_DIM);
        const float* Wsel = imagHalf ? Ci : Cr;
        const int kbase = imagHalf ? (k0 - N_DIM) : k0;
        const float sgn = imagHalf ? -1.f : 1.f;

#pragma unroll
        for (int i = 0; i < 2; i++) {
            int r = aRow + i * 64;
            float4 v = *(const float4*)(Aptr + (size_t)r * K_DIM + k0 + aCol4);
            As[aCol4 + 0][r] = v.x;
            As[aCol4 + 1][r] = v.y;
            As[aCol4 + 2][r] = v.z;
            As[aCol4 + 3][r] = v.w;
        }
#pragma unroll
        for (int i = 0; i < 2; i++) {
            int r = bRow + i * 8;
            float4 v = *(const float4*)(Wsel + (size_t)(kbase + r) * N_OUT + bn0 + bCol4);
            v.x *= sgn; v.y *= sgn; v.z *= sgn; v.w *= sgn;
            *(float4*)&Bs[r][bCol4] = v;
        }
        __syncthreads();

#pragma unroll
        for (int k = 0; k < BK; k++) {
            float ra[TM], rb[TN];
#pragma unroll
            for (int i = 0; i < TM; i++) ra[i] = As[k][trow * TM + i];
#pragma unroll
            for (int j = 0; j < TN; j++) rb[j] = Bs[k][tcol * TN + j];
#pragma unroll
            for (int i = 0; i < TM; i++)
#pragma unroll
                for (int j = 0; j < TN; j++)
                    acc[i][j] = fmaf(ra[i], rb[j], acc[i][j]);
        }
        __syncthreads();
    }

    float* Cp = Y + (size_t)(bm0 + trow * TM) * N_OUT + bn0 + tcol * TN;
#pragma unroll
    for (int i = 0; i < TM; i++) {
#pragma unroll
        for (int j = 0; j < TN; j += 4) {
            float4 v = make_float4(acc[i][j], acc[i][j+1], acc[i][j+2], acc[i][j+3]);
            *(float4*)(Cp + (size_t)i * N_OUT + j) = v;
        }
    }
}

// ---------------------------------------------------------------------------
// Launch: inputs in metadata order:
//   0: u (B,L,H) f32   1: lenghts (B,) i32   2: nu_log (N,) f32
//   3: theta_log (N,)  4: Br (H,N)           5: Bi (H,N)
//   6: Cr (N,H)        7: Ci (N,H)
// Output: y (B,L,H) f32
// ---------------------------------------------------------------------------
extern "C" void kernel_launch(void* const* d_in, const int* in_sizes, int n_in,
                              void* d_out, int out_size)
{
    const float* u        = (const float*)d_in[0];
    const int*   lengths  = (const int*)d_in[1];
    const float* nu_log   = (const float*)d_in[2];
    const float* theta_log= (const float*)d_in[3];
    const float* Br       = (const float*)d_in[4];
    const float* Bi       = (const float*)d_in[5];
    const float* Cr       = (const float*)d_in[6];
    const float* Ci       = (const float*)d_in[7];
    float* y = (float*)d_out;

    dim3 gemm_grid(N_OUT / BN, M_ROWS / BM);   // (8, 128)

    gemm1_kernel<<<gemm_grid, NTHREADS>>>(u, Br, Bi);

    int elem_threads = 256;
    int elem_blocks = (L_SEQ * N_DIM + elem_threads - 1) / elem_threads;  // 4096
    lru_elem_kernel<<<elem_blocks, elem_threads>>>(lengths, nu_log, theta_log);

    gemm2_kernel<<<gemm_grid, NTHREADS>>>(Cr, Ci, y);
}

// round 5
// speedup vs baseline: 2.1013x; 2.1013x over previous
#include <cuda_runtime.h>
#include <cuda_bf16.h>
#include <math.h>
#include <stdint.h>

// ---------------------------------------------------------------------------
// Problem constants
// ---------------------------------------------------------------------------
#define B_SZ   8
#define L_SEQ  2048
#define H_DIM  1024
#define N_DIM  512
#define M_ROWS 16384            // B*L
#define K_TOT  3072             // 3x1024 (split-bf16 folded K)
#define N_OUT  1024

// GEMM config (mma.sync path — tcgen05 is not encodable under this harness's
// compute_103 PTX target, so we use the sm_80-class HMMA pipeline)
#define BM 128
#define BN 128
#define BK 32                   // bf16 elems per stage (64 bytes per row)
#define NSTAGES 4
#define KITERS (K_TOT / BK)     // 96
#define GEMM_THREADS 256

// Padded smem rows: 32 bf16 = 64B data + 16B pad = 80B (keeps 16B alignment,
// conflict-free ldmatrix: 8 consecutive rows hit banks 0,20,8,28,16,4,24,12)
#define ROWB 80
#define TILEB (128 * ROWB)      // 10240 B per operand tile
#define STAGEB (2 * TILEB)      // 20480 B per stage
#define SMEM_DYN (NSTAGES * STAGEB)   // 81920 B

// ---------------------------------------------------------------------------
// Static device buffers (allocation-free scratch)
// ---------------------------------------------------------------------------
__device__ __nv_bfloat16 g_A[(size_t)M_ROWS * K_TOT];       // 96 MB
__device__ __nv_bfloat16 g_B1[(size_t)N_OUT * K_TOT];       // 6 MB
__device__ __nv_bfloat16 g_B2[(size_t)N_OUT * K_TOT];       // 6 MB
__device__ float         g_scratch[(size_t)M_ROWS * N_OUT]; // 64 MB (Bu f32)

// ---------------------------------------------------------------------------
// PTX helpers (sm_80-class only — all legal on base compute_103 target)
// ---------------------------------------------------------------------------
__device__ __forceinline__ uint32_t smem_u32(const void* p) {
    uint32_t a;
    asm("{ .reg .u64 t; cvta.to.shared.u64 t, %1; cvt.u32.u64 %0, t; }" : "=r"(a) : "l"(p));
    return a;
}
__device__ __forceinline__ void cp_async16(uint32_t saddr, const void* g) {
    asm volatile("cp.async.cg.shared.global [%0], [%1], 16;" :: "r"(saddr), "l"(g) : "memory");
}
#define CP_COMMIT() asm volatile("cp.async.commit_group;" ::: "memory")
template <int N> __device__ __forceinline__ void cp_wait_group() {
    asm volatile("cp.async.wait_group %0;" :: "n"(N) : "memory");
}
__device__ __forceinline__ void ldmx4(uint32_t* r, uint32_t addr) {
    asm volatile("ldmatrix.sync.aligned.m8n8.x4.shared.b16 {%0,%1,%2,%3}, [%4];"
                 : "=r"(r[0]), "=r"(r[1]), "=r"(r[2]), "=r"(r[3]) : "r"(addr));
}
__device__ __forceinline__ void mma16816(float* d, const uint32_t* a,
                                         uint32_t b0, uint32_t b1) {
    asm volatile("mma.sync.aligned.m16n8k16.row.col.f32.bf16.bf16.f32 "
                 "{%0,%1,%2,%3}, {%4,%5,%6,%7}, {%8,%9}, {%0,%1,%2,%3};"
                 : "+f"(d[0]), "+f"(d[1]), "+f"(d[2]), "+f"(d[3])
                 : "r"(a[0]), "r"(a[1]), "r"(a[2]), "r"(a[3]), "r"(b0), "r"(b1));
}

// ---------------------------------------------------------------------------
// GEMM: C(f32, 16384x1024) = g_A (bf16, MxK K-major) @ Bmat(bf16, NxK K-major)^T
// 128x128 CTA tile, 4-stage cp.async pipeline, mma.sync.m16n8k16 HMMA.
// Warps: 2(m) x 4(n); warp tile 64x32.
// ---------------------------------------------------------------------------
__global__ __launch_bounds__(GEMM_THREADS, 2)
void gemm_mma_kernel(const __nv_bfloat16* __restrict__ Bmat,
                     float* __restrict__ C)
{
    extern __shared__ char smem_raw[];
    const uint32_t sbase = smem_u32(smem_raw);

    const int tid  = threadIdx.x;
    const int wid  = tid >> 5;
    const int lane = tid & 31;
    const int wm   = wid >> 2;          // 0..1  (m)
    const int wn   = wid & 3;           // 0..3  (n)
    const int bn0  = blockIdx.x * BN;
    const int bm0  = blockIdx.y * BM;

    const char* gA = (const char*)g_A  + (size_t)bm0 * (K_TOT * 2);
    const char* gB = (const char*)Bmat + (size_t)bn0 * (K_TOT * 2);

    // cp.async mapping: 4 threads per 64B row, 64 rows per pass, 2 passes
    const int lrow = tid >> 2;           // 0..63
    const int lcol = (tid & 3) * 16;     // 0,16,32,48

    auto load_stage = [&](int s, int kiter) {
        const uint32_t sa = sbase + s * STAGEB;
        const uint32_t sb = sa + TILEB;
        const size_t kb = (size_t)kiter * (BK * 2);
#pragma unroll
        for (int p = 0; p < 2; p++) {
            const int r = lrow + p * 64;
            const size_t gofs = (size_t)r * (K_TOT * 2) + kb + lcol;
            const uint32_t sofs = r * ROWB + lcol;
            cp_async16(sa + sofs, gA + gofs);
            cp_async16(sb + sofs, gB + gofs);
        }
    };

    // ldmatrix fragment base offsets (per-thread)
    const int l16 = lane & 15;
    const int lh  = lane >> 4;
    const uint32_t a_off = (uint32_t)((wm * 64 + l16) * ROWB + lh * 16);
    const uint32_t b_off = (uint32_t)((wn * 32 + l16) * ROWB + lh * 16);

    float acc[4][4][4];
#pragma unroll
    for (int mi = 0; mi < 4; mi++)
#pragma unroll
        for (int ni = 0; ni < 4; ni++)
#pragma unroll
            for (int q = 0; q < 4; q++) acc[mi][ni][q] = 0.f;

    // Prologue
#pragma unroll
    for (int s = 0; s < NSTAGES - 1; s++) { load_stage(s, s); CP_COMMIT(); }

    for (int j = 0; j < KITERS; j++) {
        cp_wait_group<NSTAGES - 2>();
        __syncthreads();

        const int s = j & (NSTAGES - 1);
        const int jn = j + NSTAGES - 1;
        if (jn < KITERS) load_stage(jn & (NSTAGES - 1), jn);
        CP_COMMIT();

        const uint32_t sa = sbase + s * STAGEB;
        const uint32_t sb = sa + TILEB;
#pragma unroll
        for (int ks = 0; ks < 2; ks++) {                 // 2 x k16 per stage
            const uint32_t kb = ks * 32;                  // byte offset (16 bf16)
            uint32_t ar[4][4];
#pragma unroll
            for (int mi = 0; mi < 4; mi++)
                ldmx4(ar[mi], sa + a_off + mi * 16 * ROWB + kb);
            uint32_t br0[4], br1[4];
            ldmx4(br0, sb + b_off + kb);
            ldmx4(br1, sb + b_off + 16 * ROWB + kb);
#pragma unroll
            for (int mi = 0; mi < 4; mi++) {
                mma16816(acc[mi][0], ar[mi], br0[0], br0[2]);
                mma16816(acc[mi][1], ar[mi], br0[1], br0[3]);
                mma16816(acc[mi][2], ar[mi], br1[0], br1[2]);
                mma16816(acc[mi][3], ar[mi], br1[1], br1[3]);
            }
        }
    }

    // Epilogue: d-frag (m16n8): d0,d1 -> (row=lane/4, col=2*(lane%4)); d2,d3 -> row+8
    const int r0 = lane >> 2;
    const int c0 = (lane & 3) * 2;
    const int mbase = bm0 + wm * 64;
    const int nbase = bn0 + wn * 32;
#pragma unroll
    for (int mi = 0; mi < 4; mi++) {
#pragma unroll
        for (int ni = 0; ni < 4; ni++) {
            float* p = C + (size_t)(mbase + mi * 16 + r0) * N_OUT + nbase + ni * 8 + c0;
            *(float2*)p = make_float2(acc[mi][ni][0], acc[mi][ni][1]);
            *(float2*)(p + 8 * N_OUT) = make_float2(acc[mi][ni][2], acc[mi][ni][3]);
        }
    }
}

// ---------------------------------------------------------------------------
// pack_A1: u (f32, 16384x1024) -> g_A = [hi | hi | lo] (bf16, 16384x3072)
// ---------------------------------------------------------------------------
__global__ __launch_bounds__(256)
void pack_A1_kernel(const float* __restrict__ u)
{
    const int idx = blockIdx.x * blockDim.x + threadIdx.x;   // over M_ROWS*512 pairs
    if (idx >= M_ROWS * 512) return;
    const int r  = idx >> 9;
    const int np = idx & 511;
    const float2 v = *(const float2*)(u + (size_t)r * 1024 + 2 * np);
    __nv_bfloat16 h0 = __float2bfloat16_rn(v.x);
    __nv_bfloat16 h1 = __float2bfloat16_rn(v.y);
    __nv_bfloat162 hi; hi.x = h0; hi.y = h1;
    __nv_bfloat162 lo;
    lo.x = __float2bfloat16_rn(v.x - __bfloat162float(h0));
    lo.y = __float2bfloat16_rn(v.y - __bfloat162float(h1));
    __nv_bfloat162* row = (__nv_bfloat162*)(g_A + (size_t)r * K_TOT);
    row[np]        = hi;      // k = 2np
    row[512 + np]  = hi;      // k = 1024 + 2np
    row[1024 + np] = lo;      // k = 2048 + 2np
}

// ---------------------------------------------------------------------------
// pack_B: weights -> B'[n][k] = [hi(k) | lo(k-1024) | hi(k-2048)] (K-major)
// ---------------------------------------------------------------------------
__global__ __launch_bounds__(256)
void pack_B1_kernel(const float* __restrict__ Br, const float* __restrict__ Bi)
{
    __shared__ float tile[32][33];
    const int k0 = blockIdx.y * 32, n0 = blockIdx.x * 32;
    const int tx = threadIdx.x, ty = threadIdx.y;       // (32, 8)
#pragma unroll
    for (int j = 0; j < 32; j += 8) {
        const int k = k0 + ty + j, n = n0 + tx;
        tile[ty + j][tx] = (n < N_DIM) ? Br[(size_t)k * N_DIM + n]
                                       : Bi[(size_t)k * N_DIM + (n - N_DIM)];
    }
    __syncthreads();
#pragma unroll
    for (int j = 0; j < 32; j += 8) {
        const int n = n0 + ty + j, k = k0 + tx;
        const float w = tile[tx][ty + j];
        __nv_bfloat16 h = __float2bfloat16_rn(w);
        __nv_bfloat16 l = __float2bfloat16_rn(w - __bfloat162float(h));
        __nv_bfloat16* row = g_B1 + (size_t)n * K_TOT;
        row[k]        = h;
        row[1024 + k] = l;
        row[2048 + k] = h;
    }
}

__global__ __launch_bounds__(256)
void pack_B2_kernel(const float* __restrict__ Cr, const float* __restrict__ Ci)
{
    __shared__ float tile[32][33];
    const int k0 = blockIdx.y * 32, n0 = blockIdx.x * 32;
    const int tx = threadIdx.x, ty = threadIdx.y;
#pragma unroll
    for (int j = 0; j < 32; j += 8) {
        const int k = k0 + ty + j, n = n0 + tx;
        tile[ty + j][tx] = (k < N_DIM) ? Cr[(size_t)k * N_OUT + n]
                                       : -Ci[(size_t)(k - N_DIM) * N_OUT + n];
    }
    __syncthreads();
#pragma unroll
    for (int j = 0; j < 32; j += 8) {
        const int n = n0 + ty + j, k = k0 + tx;
        const float w = tile[tx][ty + j];
        __nv_bfloat16 h = __float2bfloat16_rn(w);
        __nv_bfloat16 l = __float2bfloat16_rn(w - __bfloat162float(h));
        __nv_bfloat16* row = g_B2 + (size_t)n * K_TOT;
        row[k]        = h;
        row[1024 + k] = l;
        row[2048 + k] = h;
    }
}

// ---------------------------------------------------------------------------
// Elementwise + batch cumsum, fused with split-bf16 pack of x into g_A.
// g_scratch row r=b*L+l: cols [0,512)=Bu_r, [512,1024)=Bu_i.
// ---------------------------------------------------------------------------
__global__ __launch_bounds__(256)
void lru_elem_pack_kernel(const int* __restrict__ lengths,
                          const float* __restrict__ nu_log,
                          const float* __restrict__ theta_log)
{
    const int idx = blockIdx.x * blockDim.x + threadIdx.x;   // L_SEQ * 256 pairs
    if (idx >= L_SEQ * 256) return;
    const int l  = idx >> 8;
    const int np = idx & 255;
    const int n  = 2 * np;

    float lamlog[2], argv[2];
#pragma unroll
    for (int c = 0; c < 2; c++) {
        const float lam_mod = expf(-expf(__ldg(&nu_log[n + c])));
        lamlog[c] = logf(lam_mod);
        argv[c]   = expf(__ldg(&theta_log[n + c]));
    }

    float2 vr[B_SZ], vi[B_SZ];
#pragma unroll
    for (int b = 0; b < B_SZ; b++) {
        const float* sr = g_scratch + ((size_t)(b * L_SEQ + l)) * N_OUT;
        vr[b] = *(const float2*)(sr + n);
        vi[b] = *(const float2*)(sr + N_DIM + n);
    }

    float xr0 = 0.f, xr1 = 0.f, xi0 = 0.f, xi1 = 0.f;
#pragma unroll
    for (int b = 0; b < B_SZ; b++) {
        const float e = fmaxf((float)__ldg(&lengths[b]) - (float)(l + 1), 0.f);
        float mag, s, c_;
        mag = expf(e * lamlog[0]); sincosf(e * argv[0], &s, &c_);
        float Lr = mag * c_, Li = mag * s;
        xr0 += Lr * vr[b].x - Li * vi[b].x;
        xi0 += Lr * vi[b].x + Li * vr[b].x;
        mag = expf(e * lamlog[1]); sincosf(e * argv[1], &s, &c_);
        Lr = mag * c_; Li = mag * s;
        xr1 += Lr * vr[b].y - Li * vi[b].y;
        xi1 += Lr * vi[b].y + Li * vr[b].y;

        __nv_bfloat16 hr0 = __float2bfloat16_rn(xr0), hr1 = __float2bfloat16_rn(xr1);
        __nv_bfloat16 hi0 = __float2bfloat16_rn(xi0), hi1 = __float2bfloat16_rn(xi1);
        __nv_bfloat162 hr2; hr2.x = hr0; hr2.y = hr1;
        __nv_bfloat162 hi2; hi2.x = hi0; hi2.y = hi1;
        __nv_bfloat162 lr2, li2;
        lr2.x = __float2bfloat16_rn(xr0 - __bfloat162float(hr0));
        lr2.y = __float2bfloat16_rn(xr1 - __bfloat162float(hr1));
        li2.x = __float2bfloat16_rn(xi0 - __bfloat162float(hi0));
        li2.y = __float2bfloat16_rn(xi1 - __bfloat162float(hi1));

        __nv_bfloat162* row = (__nv_bfloat162*)(g_A + ((size_t)(b * L_SEQ + l)) * K_TOT);
        row[np]         = hr2;   // k = n          (hi xr)
        row[256 + np]   = hi2;   // k = 512 + n    (hi xi)
        row[512 + np]   = hr2;   // k = 1024 + n
        row[768 + np]   = hi2;   // k = 1536 + n
        row[1024 + np]  = lr2;   // k = 2048 + n   (lo xr)
        row[1280 + np]  = li2;   // k = 2560 + n   (lo xi)
    }
}

// ---------------------------------------------------------------------------
// Launch. Inputs: 0:u 1:lenghts 2:nu_log 3:theta_log 4:Br 5:Bi 6:Cr 7:Ci
// Output: y (B,L,H) f32
// ---------------------------------------------------------------------------
extern "C" void kernel_launch(void* const* d_in, const int* in_sizes, int n_in,
                              void* d_out, int out_size)
{
    const float* u         = (const float*)d_in[0];
    const int*   lengths   = (const int*)d_in[1];
    const float* nu_log    = (const float*)d_in[2];
    const float* theta_log = (const float*)d_in[3];
    const float* Br        = (const float*)d_in[4];
    const float* Bi        = (const float*)d_in[5];
    const float* Cr        = (const float*)d_in[6];
    const float* Ci        = (const float*)d_in[7];
    float* y = (float*)d_out;

    cudaFuncSetAttribute(gemm_mma_kernel,
                         cudaFuncAttributeMaxDynamicSharedMemorySize, SMEM_DYN);

    void *pB1 = nullptr, *pB2 = nullptr, *pS = nullptr;
    cudaGetSymbolAddress(&pB1, g_B1);
    cudaGetSymbolAddress(&pB2, g_B2);
    cudaGetSymbolAddress(&pS,  g_scratch);

    // 1. Pack A' and both weight matrices
    pack_A1_kernel<<<(M_ROWS * 512) / 256, 256>>>(u);
    dim3 pb(32, 8), pg(32, 32);
    pack_B1_kernel<<<pg, pb>>>(Br, Bi);
    pack_B2_kernel<<<pg, pb>>>(Cr, Ci);

    // 2. GEMM1: Bu = A' @ B1'^T  -> g_scratch (f32)
    dim3 gg(N_OUT / BN, M_ROWS / BM);   // (8, 128)
    gemm_mma_kernel<<<gg, GEMM_THREADS, SMEM_DYN>>>(
        (const __nv_bfloat16*)pB1, (float*)pS);

    // 3. Elementwise Lambda^e * Bu + batch cumsum, packed back into g_A
    lru_elem_pack_kernel<<<(L_SEQ * 256) / 256, 256>>>(lengths, nu_log, theta_log);

    // 4. GEMM2: y = A' @ B2'^T
    gemm_mma_kernel<<<gg, GEMM_THREADS, SMEM_DYN>>>(
        (const __nv_bfloat16*)pB2, y);
}